// round 1
// baseline (speedup 1.0000x reference)
#include <cuda_runtime.h>
#include <math.h>
#include <stdint.h>

// Problem constants
#define BN 1024
#define QN 32768
#define DN 1024

// ---------------- device scratch (static globals; no allocation) -------------
__device__ float g_sim[(size_t)BN * QN];     // 128 MB sim matrix
__device__ int   g_k1a[BN];                  // anchor level-1 keys
__device__ unsigned char g_act2[BN];         // anchor active at level 2
__device__ unsigned char g_act3[BN];         // anchor active at level 3
__device__ unsigned char g_pres1[32768];     // level-1 key present among (all) anchors
__device__ unsigned char g_pres2[1024];      // level-2 key present among active2 anchors
__device__ int   g_qinfo[QN];                // queue: key1 | qa2<<20 | qa3<<21
__device__ float g_rowloss[3][BN];
__device__ int   g_rowpos[3][BN];

// ---------------- anchor prep: keys, dedup actives, presence sets ------------
__global__ void prep_anchors(const int* __restrict__ labels) {
    __shared__ int sk[BN];
    __shared__ unsigned char sa2[BN];
    int i = threadIdx.x;  // 1024 threads, one per anchor

    // zero presence sets (same block writes them later; sync below orders it)
    for (int t = i; t < 32768; t += BN) g_pres1[t] = 0;
    if (i < 1024) g_pres2[i] = 0;

    int l0 = labels[i * 4 + 0];
    int l1 = labels[i * 4 + 1];
    int l2 = labels[i * 4 + 2];
    int k1 = l0 * 1024 + l1 * 32 + l2;   // base-32 encoding (labels < 20)
    sk[i] = k1;
    __syncthreads();

    // level-1 dedup: keep LAST index with this key (torch unique last-occurrence)
    bool a2 = true;
    for (int j = i + 1; j < BN; j++) {
        if (sk[j] == k1) { a2 = false; break; }
    }
    sa2[i] = a2 ? 1 : 0;
    __syncthreads();

    // level-2 dedup among active2: keep max key1 within equal key2 group
    bool a3 = a2;
    if (a2) {
        int k2 = k1 >> 5;
        for (int j = 0; j < BN; j++) {
            if (sa2[j] && ((sk[j] >> 5) == k2) && sk[j] > k1) { a3 = false; break; }
        }
    }
    g_k1a[i] = k1;
    g_act2[i] = a2 ? 1 : 0;
    g_act3[i] = a3 ? 1 : 0;

    g_pres1[k1] = 1;                 // level-1 match uses ALL anchors
    if (a2) g_pres2[k1 >> 5] = 1;    // level-2 match uses active2 anchors
}

// ---------------- queue prep: keys + per-level active flags ------------------
__global__ void prep_queue(const int* __restrict__ lq) {
    int j = blockIdx.x * blockDim.x + threadIdx.x;
    if (j >= QN) return;
    int l0 = lq[j * 4 + 0];
    int l1 = lq[j * 4 + 1];
    int l2 = lq[j * 4 + 2];
    int k1 = l0 * 1024 + l1 * 32 + l2;
    int qa2 = g_pres1[k1] ? 0 : 1;                       // removed if matched @ level 1
    int qa3 = (qa2 && !g_pres2[k1 >> 5]) ? 1 : 0;        // removed if matched @ level 2
    g_qinfo[j] = k1 | (qa2 << 20) | (qa3 << 21);
}

// ---------------- SGEMM: sim = (F @ FQ^T) / 0.07 ------------------------------
// 128x128 block tile, 256 threads, 8x8 per thread, K-step 16.
__global__ void __launch_bounds__(256) gemm_kernel(const float* __restrict__ A,
                                                   const float* __restrict__ Bq) {
    __shared__ float As[16][128];
    __shared__ float Bs[16][128];

    int m0 = blockIdx.y * 128;
    int n0 = blockIdx.x * 128;
    int tid = threadIdx.x;
    int tx = tid & 15;
    int ty = tid >> 4;

    float acc[8][8];
#pragma unroll
    for (int i = 0; i < 8; i++)
#pragma unroll
        for (int j = 0; j < 8; j++) acc[i][j] = 0.f;

    for (int k0 = 0; k0 < DN; k0 += 16) {
#pragma unroll
        for (int it = 0; it < 2; it++) {
            int f4 = tid * 2 + it;            // 0..511
            int row = f4 >> 2;                // 0..127
            int kk = (f4 & 3) * 4;            // 0,4,8,12
            float4 va = *(const float4*)&A[(size_t)(m0 + row) * DN + k0 + kk];
            As[kk + 0][row] = va.x; As[kk + 1][row] = va.y;
            As[kk + 2][row] = va.z; As[kk + 3][row] = va.w;
            float4 vb = *(const float4*)&Bq[(size_t)(n0 + row) * DN + k0 + kk];
            Bs[kk + 0][row] = vb.x; Bs[kk + 1][row] = vb.y;
            Bs[kk + 2][row] = vb.z; Bs[kk + 3][row] = vb.w;
        }
        __syncthreads();

#pragma unroll
        for (int k = 0; k < 16; k++) {
            float ra[8], rb[8];
            float4 a0 = *(const float4*)&As[k][ty * 8 + 0];
            float4 a1 = *(const float4*)&As[k][ty * 8 + 4];
            ra[0] = a0.x; ra[1] = a0.y; ra[2] = a0.z; ra[3] = a0.w;
            ra[4] = a1.x; ra[5] = a1.y; ra[6] = a1.z; ra[7] = a1.w;
            float4 b0 = *(const float4*)&Bs[k][tx * 8 + 0];
            float4 b1 = *(const float4*)&Bs[k][tx * 8 + 4];
            rb[0] = b0.x; rb[1] = b0.y; rb[2] = b0.z; rb[3] = b0.w;
            rb[4] = b1.x; rb[5] = b1.y; rb[6] = b1.z; rb[7] = b1.w;
#pragma unroll
            for (int i = 0; i < 8; i++)
#pragma unroll
                for (int j = 0; j < 8; j++)
                    acc[i][j] = fmaf(ra[i], rb[j], acc[i][j]);
        }
        __syncthreads();
    }

    const float invT = 1.0f / 0.07f;
#pragma unroll
    for (int i = 0; i < 8; i++) {
        size_t base = (size_t)(m0 + ty * 8 + i) * QN + n0 + tx * 8;
        float4 o0 = make_float4(acc[i][0] * invT, acc[i][1] * invT,
                                acc[i][2] * invT, acc[i][3] * invT);
        float4 o1 = make_float4(acc[i][4] * invT, acc[i][5] * invT,
                                acc[i][6] * invT, acc[i][7] * invT);
        *(float4*)&g_sim[base + 0] = o0;
        *(float4*)&g_sim[base + 4] = o1;
    }
}

// ---------------- per-row reductions (3 levels) -------------------------------
__global__ void __launch_bounds__(256) row_reduce() {
    int i = blockIdx.x;
    const float* __restrict__ row = &g_sim[(size_t)i * QN];
    int k1 = g_k1a[i];
    int a2 = g_act2[i];
    int a3 = g_act3[i];
    int k2 = k1 >> 5;
    int k3 = k1 >> 10;
    int t = threadIdx.x;

    __shared__ float rbuf[256];

    // Pass A: global row max (lm1). Per-level maxima cancel analytically.
    float m1 = -INFINITY;
    for (int j = t; j < QN; j += 256) m1 = fmaxf(m1, row[j]);
    rbuf[t] = m1;
    __syncthreads();
    for (int s = 128; s > 0; s >>= 1) {
        if (t < s) rbuf[t] = fmaxf(rbuf[t], rbuf[t + s]);
        __syncthreads();
    }
    float lm = rbuf[0];
    __syncthreads();

    // Pass B: exp sums per active set + matched sums/counts per level
    float S1 = 0.f, S2 = 0.f, S3 = 0.f;
    float P1 = 0.f, P2 = 0.f, P3 = 0.f;
    float c1 = 0.f, c2 = 0.f, c3 = 0.f;
    for (int j = t; j < QN; j += 256) {
        float s = row[j];
        int qi = g_qinfo[j];
        float e = __expf(s - lm);
        int qk = qi & 0xFFFF;
        int qa2 = (qi >> 20) & 1;
        int qa3 = (qi >> 21) & 1;
        S1 += e;
        if (qa2) S2 += e;
        if (qa3) S3 += e;
        if (qk == k1) { P1 += s; c1 += 1.f; }
        if (a2 && qa2 && ((qk >> 5) == k2)) { P2 += s; c2 += 1.f; }
        if (a3 && qa3 && ((qk >> 10) == k3)) { P3 += s; c3 += 1.f; }
    }

    // deterministic tree reductions of the 9 accumulators
    float vals[9] = {S1, S2, S3, P1, P2, P3, c1, c2, c3};
    __shared__ float res[9];
#pragma unroll
    for (int v = 0; v < 9; v++) {
        rbuf[t] = vals[v];
        __syncthreads();
        for (int s = 128; s > 0; s >>= 1) {
            if (t < s) rbuf[t] += rbuf[t + s];
            __syncthreads();
        }
        if (t == 0) res[v] = rbuf[0];
        __syncthreads();
    }

    if (t == 0) {
#pragma unroll
        for (int l = 0; l < 3; l++) {
            float S = res[l];
            float P = res[3 + l];
            float c = res[6 + l];
            float loss = 0.f;
            if (c > 0.f) {
                // sum_matched log_prob = P - c*(lm + log S'); lm_l cancels.
                float mlpp = (P - c * (lm + logf(S))) / (c + 1e-12f);
                loss = -mlpp;   // TEMP/BASE_TEMP = 1
            }
            g_rowloss[l][i] = loss;
            g_rowpos[l][i] = (c > 0.f) ? 1 : 0;
        }
    }
}

// ---------------- finalize: layer losses + hmce combination -------------------
__global__ void __launch_bounds__(512) finalize(float* __restrict__ out) {
    __shared__ float sl[512];
    __shared__ float sn[512];
    __shared__ float layer[3];
    int t = threadIdx.x;
    for (int l = 0; l < 3; l++) {
        sl[t] = g_rowloss[l][t] + g_rowloss[l][t + 512];
        sn[t] = (float)(g_rowpos[l][t] + g_rowpos[l][t + 512]);
        __syncthreads();
        for (int s = 256; s > 0; s >>= 1) {
            if (t < s) { sl[t] += sl[t + s]; sn[t] += sn[t + s]; }
            __syncthreads();
        }
        if (t == 0) layer[l] = sl[0] / (sn[0] + 1e-12f);
        __syncthreads();
    }
    if (t == 0) {
        const float w[3] = {2.0f, 1.41421356237309515f, 1.25992104989487319f};
        float ml = -INFINITY;
        float cum = 0.f;
#pragma unroll
        for (int l = 0; l < 3; l++) {
            float ll = fmaxf(ml, layer[l]);
            cum += w[l] * ll;
            ml = fmaxf(ml, ll);
        }
        out[0] = cum;
    }
}

// ---------------- launch ------------------------------------------------------
extern "C" void kernel_launch(void* const* d_in, const int* in_sizes, int n_in,
                              void* d_out, int out_size) {
    const float* f  = (const float*)d_in[0];   // [1024, 1024]
    const int*   la = (const int*)d_in[1];     // [1024, 4]
    const float* fq = (const float*)d_in[2];   // [32768, 1024]
    const int*   lq = (const int*)d_in[3];     // [32768, 4]
    float* out = (float*)d_out;

    prep_anchors<<<1, BN>>>(la);
    prep_queue<<<QN / 256, 256>>>(lq);
    dim3 grid(QN / 128, BN / 128);
    gemm_kernel<<<grid, 256>>>(f, fq);
    row_reduce<<<BN, 256>>>();
    finalize<<<1, 512>>>(out);
}

// round 5
// speedup vs baseline: 4.8736x; 4.8736x over previous
#include <cuda_runtime.h>
#include <cuda_bf16.h>
#include <math.h>
#include <stdint.h>

#define BN 1024
#define QN 32768
#define DN 1024
#define TM 128          // CTA M tile
#define TN 256          // CTA N tile
#define KC 64           // K chunk (bf16 elems) = 128 bytes per row
#define NCHUNK (DN / KC)
#define NT (QN / TN)    // 128 n-tiles

// ---------------- device scratch (static globals; no allocation) -------------
__device__ __nv_bfloat16 g_abf[(size_t)BN * DN];
__device__ __nv_bfloat16 g_bbf[(size_t)QN * DN];
__device__ int   g_k1a[BN];
__device__ unsigned char g_act2[BN];
__device__ unsigned char g_act3[BN];
__device__ unsigned char g_pres1[32768];
__device__ unsigned char g_pres2[1024];
__device__ int   g_qinfo[QN];
__device__ float g_part[(size_t)BN * NT * 9];   // per (row, n-tile) partials
__device__ float g_rowloss[3][BN];
__device__ int   g_rowpos[3][BN];

// ---------------- small PTX helpers ------------------------------------------
__device__ __forceinline__ uint32_t smem_u32(const void* p) {
    uint32_t a;
    asm("{ .reg .u64 t; cvta.to.shared.u64 t, %1; cvt.u32.u64 %0, t; }" : "=r"(a) : "l"(p));
    return a;
}
// SW128 swizzle of (row*128 + kbyte), kbyte < 128
#define SW128(o) ((o) ^ (((o) >> 3) & 0x70))

__device__ __forceinline__ void cpasync16(uint32_t dst, const void* src) {
    asm volatile("cp.async.cg.shared.global [%0], [%1], 16;" :: "r"(dst), "l"(src) : "memory");
}
#define CP_COMMIT() asm volatile("cp.async.commit_group;" ::: "memory")
#define CP_WAIT0()  asm volatile("cp.async.wait_group 0;" ::: "memory")

__device__ __forceinline__ void ldmx4(uint32_t* r, uint32_t addr) {
    asm volatile("ldmatrix.sync.aligned.m8n8.x4.shared.b16 {%0,%1,%2,%3}, [%4];"
                 : "=r"(r[0]), "=r"(r[1]), "=r"(r[2]), "=r"(r[3]) : "r"(addr));
}
__device__ __forceinline__ void mma16816(float* c, const uint32_t* a,
                                         uint32_t b0, uint32_t b1) {
    asm volatile(
        "mma.sync.aligned.m16n8k16.row.col.f32.bf16.bf16.f32 "
        "{%0,%1,%2,%3}, {%4,%5,%6,%7}, {%8,%9}, {%0,%1,%2,%3};"
        : "+f"(c[0]), "+f"(c[1]), "+f"(c[2]), "+f"(c[3])
        : "r"(a[0]), "r"(a[1]), "r"(a[2]), "r"(a[3]), "r"(b0), "r"(b1));
}

// ---------------- anchor prep -------------------------------------------------
__global__ void prep_anchors(const int* __restrict__ labels) {
    __shared__ int sk[BN];
    __shared__ unsigned char sa2[BN];
    int i = threadIdx.x;
    for (int t = i; t < 32768; t += BN) g_pres1[t] = 0;
    if (i < 1024) g_pres2[i] = 0;
    int l0 = labels[i * 4 + 0], l1 = labels[i * 4 + 1], l2 = labels[i * 4 + 2];
    int k1 = l0 * 1024 + l1 * 32 + l2;
    sk[i] = k1;
    __syncthreads();
    bool a2 = true;
    for (int j = i + 1; j < BN; j++) if (sk[j] == k1) { a2 = false; break; }
    sa2[i] = a2 ? 1 : 0;
    __syncthreads();
    bool a3 = a2;
    if (a2) {
        int k2 = k1 >> 5;
        for (int j = 0; j < BN; j++)
            if (sa2[j] && ((sk[j] >> 5) == k2) && sk[j] > k1) { a3 = false; break; }
    }
    g_k1a[i] = k1; g_act2[i] = a2 ? 1 : 0; g_act3[i] = a3 ? 1 : 0;
    g_pres1[k1] = 1;
    if (a2) g_pres2[k1 >> 5] = 1;
}

// ---------------- queue prep --------------------------------------------------
__global__ void prep_queue(const int* __restrict__ lq) {
    int j = blockIdx.x * blockDim.x + threadIdx.x;
    if (j >= QN) return;
    int k1 = lq[j * 4 + 0] * 1024 + lq[j * 4 + 1] * 32 + lq[j * 4 + 2];
    int qa2 = g_pres1[k1] ? 0 : 1;
    int qa3 = (qa2 && !g_pres2[k1 >> 5]) ? 1 : 0;
    g_qinfo[j] = k1 | (qa2 << 20) | (qa3 << 21);
}

// ---------------- fp32 -> bf16 converters ------------------------------------
__global__ void conv_a(const float* __restrict__ in) {
    int i = blockIdx.x * blockDim.x + threadIdx.x;
    float4 v = ((const float4*)in)[i];
    __nv_bfloat162 lo(__float2bfloat16(v.x), __float2bfloat16(v.y));
    __nv_bfloat162 hi(__float2bfloat16(v.z), __float2bfloat16(v.w));
    uint2 o; o.x = *(unsigned*)&lo; o.y = *(unsigned*)&hi;
    ((uint2*)g_abf)[i] = o;
}
__global__ void conv_b(const float* __restrict__ in) {
    int i = blockIdx.x * blockDim.x + threadIdx.x;
    float4 v = ((const float4*)in)[i];
    __nv_bfloat162 lo(__float2bfloat16(v.x), __float2bfloat16(v.y));
    __nv_bfloat162 hi(__float2bfloat16(v.z), __float2bfloat16(v.w));
    uint2 o; o.x = *(unsigned*)&lo; o.y = *(unsigned*)&hi;
    ((uint2*)g_bbf)[i] = o;
}

// ---------------- fused GEMM + softmax/match partial reduction ----------------
// smem: A[2]: 16KB each, B[2]: 32KB each = 96KB (+1KB align slack)
static constexpr int SMEM_BYTES = 2 * (TM * KC * 2) + 2 * (TN * KC * 2) + 1024;

__device__ __forceinline__ void issue_chunk(int it, int m0, int n0,
                                            uint32_t Ab, uint32_t Bb, int tid) {
    const uint4* ag = (const uint4*)g_abf;   // 128 uint4 per row
    const uint4* bg = (const uint4*)g_bbf;
    int k8 = it * (KC / 8);                  // uint4 offset of chunk
#pragma unroll
    for (int u = 0; u < 4; u++) {            // A: 1024 16B chunks
        int idx = tid + u * 256;
        int row = idx >> 3, q = idx & 7;
        cpasync16(Ab + SW128(row * 128 + q * 16),
                  &ag[(size_t)(m0 + row) * 128 + k8 + q]);
    }
#pragma unroll
    for (int u = 0; u < 8; u++) {            // B: 2048 16B chunks
        int idx = tid + u * 256;
        int row = idx >> 3, q = idx & 7;
        cpasync16(Bb + SW128(row * 128 + q * 16),
                  &bg[(size_t)(n0 + row) * 128 + k8 + q]);
    }
    CP_COMMIT();
}

__global__ void __launch_bounds__(256) gemm_fused() {
    extern __shared__ char dsm[];
    char* base = (char*)(((uintptr_t)dsm + 1023) & ~(uintptr_t)1023);
    uint32_t sb = smem_u32(base);
    uint32_t Ab0 = sb, Ab1 = sb + 16384;
    uint32_t Bb0 = sb + 32768, Bb1 = sb + 32768 + 32768;

    int tid = threadIdx.x;
    int wid = tid >> 5, lane = tid & 31;
    int m0 = blockIdx.y * TM, n0 = blockIdx.x * TN;
    int wm0 = (wid & 3) * 32;        // warp M offset (4 m-warps)
    int wn0 = (wid >> 2) * 128;      // warp N offset (2 n-warps)

    float acc[2][16][4];
#pragma unroll
    for (int a = 0; a < 2; a++)
#pragma unroll
        for (int b = 0; b < 16; b++)
#pragma unroll
            for (int c = 0; c < 4; c++) acc[a][b][c] = 0.f;

    // precomputed lane pieces
    int arow[2];
    arow[0] = wm0 + (lane & 15);
    arow[1] = wm0 + 16 + (lane & 15);
    int akb = (lane >> 4) << 4;                       // 0 or 16
    int brow_base = wn0 + (lane & 7) + ((lane >> 4) & 1) * 8;
    int bkb = ((lane >> 3) & 1) << 4;                 // 0 or 16

    issue_chunk(0, m0, n0, Ab0, Bb0, tid);
    CP_WAIT0();
    __syncthreads();

    for (int it = 0; it < NCHUNK; it++) {
        uint32_t Ab = (it & 1) ? Ab1 : Ab0;
        uint32_t Bb = (it & 1) ? Bb1 : Bb0;
        if (it + 1 < NCHUNK)
            issue_chunk(it + 1, m0, n0, (it & 1) ? Ab0 : Ab1, (it & 1) ? Bb0 : Bb1, tid);

#pragma unroll
        for (int ks = 0; ks < 4; ks++) {
            int kb = ks * 32;
            uint32_t a[2][4];
#pragma unroll
            for (int fm = 0; fm < 2; fm++)
                ldmx4(a[fm], Ab + SW128(arow[fm] * 128 + kb + akb));
#pragma unroll
            for (int fn2 = 0; fn2 < 8; fn2++) {
                uint32_t b[4];
                ldmx4(b, Bb + SW128((brow_base + fn2 * 16) * 128 + kb + bkb));
                mma16816(acc[0][2 * fn2 + 0], a[0], b[0], b[1]);
                mma16816(acc[0][2 * fn2 + 1], a[0], b[2], b[3]);
                mma16816(acc[1][2 * fn2 + 0], a[1], b[0], b[1]);
                mma16816(acc[1][2 * fn2 + 1], a[1], b[2], b[3]);
            }
        }
        if (it + 1 < NCHUNK) CP_WAIT0();
        __syncthreads();
    }

    // -------- epilogue: per-row 9-value partial reduction --------------------
    const float invT = 1.0f / 0.07f;
    const float LM = invT;          // analytic sim upper bound (unit vectors)

    int qv[32];
#pragma unroll
    for (int fn = 0; fn < 16; fn++)
#pragma unroll
        for (int e = 0; e < 2; e++)
            qv[fn * 2 + e] = g_qinfo[n0 + wn0 + fn * 8 + (lane & 3) * 2 + e];

    float* sacc = (float*)base;     // [2 nwarp][128 rows][9], reuses A/B smem
    int nw = wid >> 2;

#pragma unroll
    for (int fm = 0; fm < 2; fm++) {
#pragma unroll
        for (int half = 0; half < 2; half++) {
            int rlocal = wm0 + fm * 16 + half * 8 + (lane >> 2);
            int rglob = m0 + rlocal;
            int k1 = g_k1a[rglob];
            int a2f = g_act2[rglob], a3f = g_act3[rglob];
            int k2 = k1 >> 5, k3 = k1 >> 10;
            float S1 = 0.f, S2 = 0.f, S3 = 0.f;
            float P1 = 0.f, P2 = 0.f, P3 = 0.f;
            float c1 = 0.f, c2 = 0.f, c3 = 0.f;
#pragma unroll
            for (int fn = 0; fn < 16; fn++) {
#pragma unroll
                for (int e = 0; e < 2; e++) {
                    float s = acc[fm][fn][half * 2 + e] * invT;
                    float ex = __expf(s - LM);
                    int qi = qv[fn * 2 + e];
                    int qk = qi & 0xFFFF;
                    int qa2 = (qi >> 20) & 1, qa3 = (qi >> 21) & 1;
                    S1 += ex;
                    if (qa2) S2 += ex;
                    if (qa3) S3 += ex;
                    if (qk == k1) { P1 += s; c1 += 1.f; }
                    if (a2f && qa2 && ((qk >> 5) == k2)) { P2 += s; c2 += 1.f; }
                    if (a3f && qa3 && ((qk >> 10) == k3)) { P3 += s; c3 += 1.f; }
                }
            }
            float rs[9] = {S1, S2, S3, P1, P2, P3, c1, c2, c3};
#pragma unroll
            for (int v = 0; v < 9; v++) {
                rs[v] += __shfl_xor_sync(0xFFFFFFFFu, rs[v], 1);
                rs[v] += __shfl_xor_sync(0xFFFFFFFFu, rs[v], 2);
            }
            if (fm == 0 && half == 0 && lane == 0) { /* no-op anchor for ordering */ }
            if ((lane & 3) == 0) {
                if (fm == 0 && half == 0) { /* first write after sync below */ }
            }
            // defer writes until after the barrier: stash via registers is
            // complex; instead barrier once before the very first write.
            if (fm == 0 && half == 0) __syncthreads();   // executed by ALL threads
#pragma unroll
            for (int v = 0; v < 9; v++)
                if ((lane & 3) == 0)
                    sacc[((size_t)nw * 128 + rlocal) * 9 + v] = rs[v];
        }
    }
    __syncthreads();

    // combine the two n-warp halves and store partials
    for (int idx = tid; idx < 128 * 9; idx += 256) {
        int row = idx / 9, v = idx - row * 9;
        g_part[((size_t)(m0 + row) * NT + blockIdx.x) * 9 + v] =
            sacc[(size_t)row * 9 + v] + sacc[(size_t)(128 + row) * 9 + v];
    }
}

// ---------------- per-row final reduction ------------------------------------
__global__ void __launch_bounds__(128) row_reduce2() {
    int i = blockIdx.x;
    int t = threadIdx.x;          // one n-tile per thread (NT == 128)
    const float LM = 1.0f / 0.07f;
    float r[9];
    const float* p = &g_part[((size_t)i * NT + t) * 9];
#pragma unroll
    for (int v = 0; v < 9; v++) r[v] = p[v];
#pragma unroll
    for (int v = 0; v < 9; v++)
#pragma unroll
        for (int o = 16; o > 0; o >>= 1)
            r[v] += __shfl_xor_sync(0xFFFFFFFFu, r[v], o);

    __shared__ float wsum[4][9];
    int wid = t >> 5, lane = t & 31;
    if (lane == 0)
#pragma unroll
        for (int v = 0; v < 9; v++) wsum[wid][v] = r[v];
    __syncthreads();

    if (t == 0) {
        float res[9];
#pragma unroll
        for (int v = 0; v < 9; v++)
            res[v] = wsum[0][v] + wsum[1][v] + wsum[2][v] + wsum[3][v];
#pragma unroll
        for (int l = 0; l < 3; l++) {
            float S = res[l], P = res[3 + l], c = res[6 + l];
            float loss = 0.f;
            if (c > 0.f) loss = -(P - c * (LM + logf(S))) / (c + 1e-12f);
            g_rowloss[l][i] = loss;
            g_rowpos[l][i] = (c > 0.f) ? 1 : 0;
        }
    }
}

// ---------------- finalize ----------------------------------------------------
__global__ void __launch_bounds__(512) finalize(float* __restrict__ out) {
    __shared__ float sl[512];
    __shared__ float sn[512];
    __shared__ float layer[3];
    int t = threadIdx.x;
    for (int l = 0; l < 3; l++) {
        sl[t] = g_rowloss[l][t] + g_rowloss[l][t + 512];
        sn[t] = (float)(g_rowpos[l][t] + g_rowpos[l][t + 512]);
        __syncthreads();
        for (int s = 256; s > 0; s >>= 1) {
            if (t < s) { sl[t] += sl[t + s]; sn[t] += sn[t + s]; }
            __syncthreads();
        }
        if (t == 0) layer[l] = sl[0] / (sn[0] + 1e-12f);
        __syncthreads();
    }
    if (t == 0) {
        const float w[3] = {2.0f, 1.41421356237309515f, 1.25992104989487319f};
        float ml = -INFINITY, cum = 0.f;
#pragma unroll
        for (int l = 0; l < 3; l++) {
            float ll = fmaxf(ml, layer[l]);
            cum += w[l] * ll;
            ml = fmaxf(ml, ll);
        }
        out[0] = cum;
    }
}

// ---------------- launch ------------------------------------------------------
extern "C" void kernel_launch(void* const* d_in, const int* in_sizes, int n_in,
                              void* d_out, int out_size) {
    const float* f  = (const float*)d_in[0];
    const int*   la = (const int*)d_in[1];
    const float* fq = (const float*)d_in[2];
    const int*   lq = (const int*)d_in[3];
    float* out = (float*)d_out;

    static int attr_done = 0;
    if (!attr_done) {
        cudaFuncSetAttribute(gemm_fused, cudaFuncAttributeMaxDynamicSharedMemorySize,
                             SMEM_BYTES);
        attr_done = 1;
    }

    prep_anchors<<<1, BN>>>(la);
    prep_queue<<<QN / 256, 256>>>(lq);
    conv_a<<<(BN * DN / 4) / 256, 256>>>(f);
    conv_b<<<(QN * DN / 4) / 256, 256>>>(fq);
    dim3 grid(QN / TN, BN / TM);
    gemm_fused<<<grid, 256, SMEM_BYTES>>>();
    row_reduce2<<<BN, 128>>>();
    finalize<<<1, 512>>>(out);
}